// round 6
// baseline (speedup 1.0000x reference)
#include <cuda_runtime.h>
#include <cuda_bf16.h>
#include <cstdint>

// Problem: B=128, N=128, D=1024, H=8, HD=128, M = B*N = 16384
#define PLANE  (16384ull * 1024ull)     // activation plane elems (bf16)
#define WPLANE (1024ull * 1024ull)      // weight plane elems (bf16)
// layout: inh(3) inl(3) ohb(7) olb(7) ath atl | whb(8) wlb(8)
__device__ __align__(1024) __nv_bfloat16 g_bf[22ull * PLANE + 16ull * WPLANE];

typedef __nv_bfloat16 bf16;

// ======================= PTX helpers =========================================
__device__ __forceinline__ uint32_t s2u(const void* p) {
    uint32_t a;
    asm("{ .reg .u64 t; cvta.to.shared.u64 t, %1; cvt.u32.u64 %0, t; }"
        : "=r"(a) : "l"(p));
    return a;
}
__device__ __forceinline__ void ldsm4(uint32_t* r, uint32_t addr) {
    asm volatile("ldmatrix.sync.aligned.m8n8.x4.shared.b16 {%0,%1,%2,%3}, [%4];"
                 : "=r"(r[0]), "=r"(r[1]), "=r"(r[2]), "=r"(r[3]) : "r"(addr));
}
__device__ __forceinline__ void ldsm4t(uint32_t* r, uint32_t addr) {
    asm volatile("ldmatrix.sync.aligned.m8n8.x4.trans.shared.b16 {%0,%1,%2,%3}, [%4];"
                 : "=r"(r[0]), "=r"(r[1]), "=r"(r[2]), "=r"(r[3]) : "r"(addr));
}
__device__ __forceinline__ void mma_bf16(float* d, const uint32_t* a, const uint32_t* b) {
    asm volatile(
        "mma.sync.aligned.m16n8k16.row.col.f32.bf16.bf16.f32 "
        "{%0,%1,%2,%3},{%4,%5,%6,%7},{%8,%9},{%0,%1,%2,%3};"
        : "+f"(d[0]), "+f"(d[1]), "+f"(d[2]), "+f"(d[3])
        : "r"(a[0]), "r"(a[1]), "r"(a[2]), "r"(a[3]), "r"(b[0]), "r"(b[1]));
}
#define CP16(dst, src) \
    asm volatile("cp.async.cg.shared.global [%0], [%1], 16;" :: "r"(dst), "l"(src))
#define CPCOMMIT() asm volatile("cp.async.commit_group;" ::: "memory")
#define CPWAIT2()  asm volatile("cp.async.wait_group 2;" ::: "memory")
#define CPWAIT0()  asm volatile("cp.async.wait_group 0;" ::: "memory")

__device__ __forceinline__ void split1(float v, bf16& h, bf16& l) {
    h = __float2bfloat16(v);
    l = __float2bfloat16(v - __bfloat162float(h));
}
__device__ __forceinline__ void packsplit2(float x0, float x1,
                                           uint32_t& hi, uint32_t& lo) {
    bf16 h0, l0, h1, l1;
    split1(x0, h0, l0); split1(x1, h1, l1);
    __nv_bfloat162 hh; hh.x = h0; hh.y = h1;
    __nv_bfloat162 ll; ll.x = l0; ll.y = l1;
    hi = *(uint32_t*)&hh; lo = *(uint32_t*)&ll;
}

// ======================= fused input split (3 inputs) ========================
__global__ __launch_bounds__(256) void split_all(
    const float* __restrict__ s0, const float* __restrict__ s1,
    const float* __restrict__ s2, bf16* __restrict__ hb, bf16* __restrict__ lb)
{
    const float* src = (blockIdx.y == 0) ? s0 : (blockIdx.y == 1) ? s1 : s2;
    bf16* h = hb + (size_t)blockIdx.y * PLANE;
    bf16* l = lb + (size_t)blockIdx.y * PLANE;
    size_t i4 = ((size_t)blockIdx.x * 256 + threadIdx.x) * 4;
    float4 v = *(const float4*)(src + i4);
    uint32_t hh0, ll0, hh1, ll1;
    packsplit2(v.x, v.y, hh0, ll0);
    packsplit2(v.z, v.w, hh1, ll1);
    *(uint32_t*)(h + i4)     = hh0; *(uint32_t*)(h + i4 + 2) = hh1;
    *(uint32_t*)(l + i4)     = ll0; *(uint32_t*)(l + i4 + 2) = ll1;
}

// ======================= fused weight transpose + split (4 weights) ==========
__global__ __launch_bounds__(256) void transpose4(
    const float* __restrict__ s0, const float* __restrict__ s1,
    const float* __restrict__ s2, const float* __restrict__ s3,
    bf16* __restrict__ hb, bf16* __restrict__ lb)
{
    const float* src = (blockIdx.z == 0) ? s0 : (blockIdx.z == 1) ? s1
                     : (blockIdx.z == 2) ? s2 : s3;
    bf16* h = hb + (size_t)blockIdx.z * WPLANE;
    bf16* l = lb + (size_t)blockIdx.z * WPLANE;
    __shared__ float t[32][33];
    int bx = blockIdx.x * 32, by = blockIdx.y * 32;
    int tx = threadIdx.x, ty = threadIdx.y;
#pragma unroll
    for (int i = ty; i < 32; i += 8)
        t[i][tx] = src[(size_t)(by + i) * 1024 + bx + tx];
    __syncthreads();
#pragma unroll
    for (int i = ty; i < 32; i += 8) {
        bf16 hh, ll;
        split1(t[tx][i], hh, ll);
        size_t o = (size_t)(bx + i) * 1024 + by + tx;
        h[o] = hh; l[o] = ll;
    }
}

// ======================= bf16-split mma.sync GEMM (cp.async, 4-stage) ========
// C = A * Bcat^T. Bcat = concatenated 1024x1024 transposed-weight planes.
// A idx(r,k) = (r/128)*131072 + (k/128)*ACB + (r%128)*ARI + (k%128)
// B plane = ct>>3; row in plane = (ct&7)*128 + r
// C (bf16): plane (ct>>3)*PLANE + (r/128)*131072 + (ct&7)*CCB + (r%128)*CRI + c
// C (f32, N=1024): plane 0, row-major via CCB/CRI.
#define GEMM_SMEM (4 * 24576)

__global__ __launch_bounds__(256, 2) void gemm_bf(
    const bf16* __restrict__ Ah, const bf16* __restrict__ Al,
    const bf16* __restrict__ Bh, const bf16* __restrict__ Bl,
    float* __restrict__ Cf, bf16* __restrict__ Ch, bf16* __restrict__ Cl,
    const float* __restrict__ bias, int ACB, int ARI, int CCB, int CRI)
{
    extern __shared__ __align__(1024) char smem[];
    const uint32_t sb = s2u(smem);
    const int tid = threadIdx.x;
    const int lane = tid & 31, wid = tid >> 5;
    const int rt = blockIdx.y, ct = blockIdx.x;
    const int bp = ct >> 3, bct = ct & 7;
    const int wm = wid & 1, wn = wid >> 1;
    const int s8 = lane >> 3, r8 = lane & 7;
    const uint32_t aLane = (uint32_t)(((s8 & 1) * 8 + r8) * 48 + (s8 >> 1) * 16);
    const uint32_t bLane = (uint32_t)(((s8 >> 1) * 8 + r8) * 48 + (s8 & 1) * 16);

    const int row = tid >> 1, half = tid & 1;
    const size_t aoff = (size_t)rt * 131072 + (size_t)row * ARI + half * 8;
    const size_t boff = (size_t)bp * WPLANE + (size_t)(bct * 128 + row) * 1024 + half * 8;
    const uint32_t dstoff = (uint32_t)(row * 48 + half * 16);

    float acc[4][4][4];
#pragma unroll
    for (int i = 0; i < 4; i++)
#pragma unroll
        for (int j = 0; j < 4; j++)
#pragma unroll
            for (int k = 0; k < 4; k++) acc[i][j][k] = 0.f;

    auto load_chunk = [&](int c) {
        const int kk = c * 16;
        const uint32_t st = sb + (uint32_t)((c & 3) * 24576) + dstoff;
        const size_t asrc = aoff + (size_t)(kk >> 7) * ACB + (kk & 127);
        const size_t bsrc = boff + kk;
        CP16(st,          Ah + asrc);
        CP16(st + 6144,   Al + asrc);
        CP16(st + 12288,  Bh + bsrc);
        CP16(st + 18432,  Bl + bsrc);
    };

    load_chunk(0); CPCOMMIT();
    load_chunk(1); CPCOMMIT();
    load_chunk(2); CPCOMMIT();

    for (int c = 0; c < 64; c++) {
        CPWAIT2();
        __syncthreads();
        if (c + 3 < 64) load_chunk(c + 3);
        CPCOMMIT();

        const uint32_t off = sb + (uint32_t)((c & 3) * 24576);
        uint32_t ah[4][4], bh[4][2], bl[4][2];
#pragma unroll
        for (int mt = 0; mt < 4; mt++)
            ldsm4(ah[mt], off + (uint32_t)((wm * 64 + mt * 16) * 48) + aLane);
#pragma unroll
        for (int g = 0; g < 2; g++) {
            uint32_t q[4];
            ldsm4(q, off + 12288u + (uint32_t)((wn * 32 + g * 16) * 48) + bLane);
            bh[g * 2][0] = q[0]; bh[g * 2][1] = q[1];
            bh[g * 2 + 1][0] = q[2]; bh[g * 2 + 1][1] = q[3];
            ldsm4(q, off + 18432u + (uint32_t)((wn * 32 + g * 16) * 48) + bLane);
            bl[g * 2][0] = q[0]; bl[g * 2][1] = q[1];
            bl[g * 2 + 1][0] = q[2]; bl[g * 2 + 1][1] = q[3];
        }
        // Sweep 1: hi*hi — 16 distinct accumulators (RAW distance 16)
#pragma unroll
        for (int mt = 0; mt < 4; mt++)
#pragma unroll
            for (int nt = 0; nt < 4; nt++)
                mma_bf16(acc[mt][nt], ah[mt], bh[nt]);
        // Sweep 2: hi*lo — 16 distinct accumulators
#pragma unroll
        for (int mt = 0; mt < 4; mt++)
#pragma unroll
            for (int nt = 0; nt < 4; nt++)
                mma_bf16(acc[mt][nt], ah[mt], bl[nt]);
        // Sweep 3: lo*hi — al loaded lazily, still distance >= 4
#pragma unroll
        for (int mt = 0; mt < 4; mt++) {
            uint32_t al[4];
            ldsm4(al, off + 6144u + (uint32_t)((wm * 64 + mt * 16) * 48) + aLane);
#pragma unroll
            for (int nt = 0; nt < 4; nt++)
                mma_bf16(acc[mt][nt], al, bh[nt]);
        }
    }

    // ---- epilogue ----
    const int g = lane >> 2, cp = (lane & 3) * 2;
    const size_t cbase = (size_t)bp * PLANE + (size_t)rt * 131072 + (size_t)bct * CCB;
#pragma unroll
    for (int mt = 0; mt < 4; mt++) {
#pragma unroll
        for (int nt = 0; nt < 4; nt++) {
            int r0 = wm * 64 + mt * 16 + g;
            int col = wn * 32 + nt * 8 + cp;
            float v0 = acc[mt][nt][0], v1 = acc[mt][nt][1];
            float v2 = acc[mt][nt][2], v3 = acc[mt][nt][3];
            size_t o0 = cbase + (size_t)r0 * CRI + col;
            size_t o1 = cbase + (size_t)(r0 + 8) * CRI + col;
            if (Cf) {
                float b0 = bias[ct * 128 + col], b1 = bias[ct * 128 + col + 1];
                *(float2*)(Cf + o0) = make_float2(v0 + b0, v1 + b1);
                *(float2*)(Cf + o1) = make_float2(v2 + b0, v3 + b1);
            } else {
                uint32_t hh, ll;
                packsplit2(v0, v1, hh, ll);
                *(uint32_t*)(Ch + o0) = hh; *(uint32_t*)(Cl + o0) = ll;
                packsplit2(v2, v3, hh, ll);
                *(uint32_t*)(Ch + o1) = hh; *(uint32_t*)(Cl + o1) = ll;
            }
        }
    }
}

// ======================= mma attention (register-resident P) =================
// One CTA per (b,h). Warp w owns rows w*16..w*16+15 (full 128 cols).
// sim = sum_s Q_s * K_s (plain 128x128 products), softmax rows, out = P * V.
// P never touches smem: sim C-fragments repack into bf16 hi/lo A-fragments.
// smem: Q stages@0 (4 x 12288: h@0 l@6144), K/V stages@49152 (4 x 8704).
#define ATT_SMEM 83968
#define ATT_KST  49152u

__global__ __launch_bounds__(256, 1) void attn_mma(
    const bf16* __restrict__ ohb, const bf16* __restrict__ olb,
    bf16* __restrict__ ath, bf16* __restrict__ atl)
{
    extern __shared__ __align__(1024) char smem[];
    const uint32_t sb = s2u(smem);
    const int tid = threadIdx.x;
    const int lane = tid & 31, w = tid >> 5;
    const size_t bhoff = (size_t)blockIdx.x * 16384;

    // plane order in ohb: 0 qw, 1 kw, 2 vw, 3 qp, 4 kp, 5 qc, 6 kc
    const int qpl[3] = { 0, 3, 5 }, kpl[3] = { 1, 4, 6 };

    const int s8 = lane >> 3, r8 = lane & 7;
    const uint32_t aLane = (uint32_t)(((s8 & 1) * 8 + r8) * 48 + (s8 >> 1) * 16);
    const uint32_t kr = (uint32_t)(lane & 15);
    const uint32_t nf = (uint32_t)((lane >> 4) * 8);
    const uint32_t wrow48 = (uint32_t)(w * 16 * 48);

    const int qrow = tid >> 1, qhalf = tid & 1;
    const uint32_t qdst = (uint32_t)(qrow * 48 + qhalf * 16);
    const int krow = tid >> 4, kseg = tid & 15;
    const uint32_t kdst = (uint32_t)(krow * 272 + kseg * 16);

    auto loadQK = [&](int it) {
        int s = it >> 3, c = it & 7;
        uint32_t qs = sb + (uint32_t)((it & 3) * 12288) + qdst;
        size_t qsrc = (size_t)qpl[s] * PLANE + bhoff + (size_t)qrow * 128 + c * 16 + qhalf * 8;
        CP16(qs,        ohb + qsrc);
        CP16(qs + 6144, olb + qsrc);
        uint32_t ks = sb + ATT_KST + (uint32_t)((it & 3) * 8704) + kdst;
        size_t ksrc = (size_t)kpl[s] * PLANE + bhoff + (size_t)(c * 16 + krow) * 128 + kseg * 8;
        CP16(ks,        ohb + ksrc);
        CP16(ks + 4352, olb + ksrc);
    };
    auto loadV = [&](int v) {
        uint32_t ks = sb + ATT_KST + (uint32_t)((v & 3) * 8704) + kdst;
        size_t ksrc = 2ull * PLANE + bhoff + (size_t)(v * 16 + krow) * 128 + kseg * 8;
        CP16(ks,        ohb + ksrc);
        CP16(ks + 4352, olb + ksrc);
    };

    float acc[16][4];
#pragma unroll
    for (int i = 0; i < 16; i++)
#pragma unroll
        for (int j = 0; j < 4; j++) acc[i][j] = 0.f;

    loadQK(0); CPCOMMIT();
    loadQK(1); CPCOMMIT();
    loadQK(2); CPCOMMIT();

    // ---- Phase 1: sim (24 iters = 3 streams x 8 k-chunks) ----
    for (int it = 0; it < 24; it++) {
        CPWAIT2();
        __syncthreads();
        if (it + 3 < 24) loadQK(it + 3);
        CPCOMMIT();

        const uint32_t qs = sb + (uint32_t)((it & 3) * 12288);
        const uint32_t ks = sb + ATT_KST + (uint32_t)((it & 3) * 8704);
        uint32_t ah[4], al[4];
        ldsm4(ah, qs + wrow48 + aLane);
        ldsm4(al, qs + 6144 + wrow48 + aLane);
        // process n8-tiles in pairs of g: 12 MMAs, same-acc distance 4
#pragma unroll
        for (int gp = 0; gp < 4; gp++) {
            uint32_t b0h[4], b0l[4], b1h[4], b1l[4];
            uint32_t a0 = ks + kr * 272 + ((2 * gp) * 16 + nf) * 2;
            uint32_t a1 = ks + kr * 272 + ((2 * gp + 1) * 16 + nf) * 2;
            ldsm4t(b0h, a0); ldsm4t(b0l, a0 + 4352);
            ldsm4t(b1h, a1); ldsm4t(b1l, a1 + 4352);
            float* c0 = acc[4 * gp],     *c1 = acc[4 * gp + 1];
            float* c2 = acc[4 * gp + 2], *c3 = acc[4 * gp + 3];
            mma_bf16(c0, ah, b0h);     mma_bf16(c1, ah, b0h + 2);
            mma_bf16(c2, ah, b1h);     mma_bf16(c3, ah, b1h + 2);
            mma_bf16(c0, al, b0h);     mma_bf16(c1, al, b0h + 2);
            mma_bf16(c2, al, b1h);     mma_bf16(c3, al, b1h + 2);
            mma_bf16(c0, ah, b0l);     mma_bf16(c1, ah, b0l + 2);
            mma_bf16(c2, ah, b1l);     mma_bf16(c3, ah, b1l + 2);
        }
    }

    // drain QK traffic, then prefetch V into stages 0..2 (overlaps softmax)
    CPWAIT0();
    __syncthreads();
    loadV(0); CPCOMMIT();
    loadV(1); CPCOMMIT();
    loadV(2); CPCOMMIT();

    // ---- Phase 2: softmax (warp-local; lane rows g and g+8) ----
    const float SC = 0.08838834764831845f;   // 128^-0.5
    float m0 = -1e30f, m1 = -1e30f;
#pragma unroll
    for (int nt = 0; nt < 16; nt++) {
#pragma unroll
        for (int j = 0; j < 4; j++) acc[nt][j] *= SC;
        m0 = fmaxf(m0, fmaxf(acc[nt][0], acc[nt][1]));
        m1 = fmaxf(m1, fmaxf(acc[nt][2], acc[nt][3]));
    }
    m0 = fmaxf(m0, __shfl_xor_sync(0xffffffffu, m0, 1));
    m0 = fmaxf(m0, __shfl_xor_sync(0xffffffffu, m0, 2));
    m1 = fmaxf(m1, __shfl_xor_sync(0xffffffffu, m1, 1));
    m1 = fmaxf(m1, __shfl_xor_sync(0xffffffffu, m1, 2));
    float sum0 = 0.f, sum1 = 0.f;
#pragma unroll
    for (int nt = 0; nt < 16; nt++) {
        acc[nt][0] = __expf(acc[nt][0] - m0); sum0 += acc[nt][0];
        acc[nt][1] = __expf(acc[nt][1] - m0); sum0 += acc[nt][1];
        acc[nt][2] = __expf(acc[nt][2] - m1); sum1 += acc[nt][2];
        acc[nt][3] = __expf(acc[nt][3] - m1); sum1 += acc[nt][3];
    }
    sum0 += __shfl_xor_sync(0xffffffffu, sum0, 1);
    sum0 += __shfl_xor_sync(0xffffffffu, sum0, 2);
    sum1 += __shfl_xor_sync(0xffffffffu, sum1, 1);
    sum1 += __shfl_xor_sync(0xffffffffu, sum1, 2);
    const float inv0 = 1.f / sum0, inv1 = 1.f / sum1;

    // ---- repack P into A-fragments (C-frag layout == A-frag layout) ----
    uint32_t ph[8][4], pl[8][4];
#pragma unroll
    for (int c = 0; c < 8; c++) {
        packsplit2(acc[2*c][0]   * inv0, acc[2*c][1]   * inv0, ph[c][0], pl[c][0]);
        packsplit2(acc[2*c][2]   * inv1, acc[2*c][3]   * inv1, ph[c][1], pl[c][1]);
        packsplit2(acc[2*c+1][0] * inv0, acc[2*c+1][1] * inv0, ph[c][2], pl[c][2]);
        packsplit2(acc[2*c+1][2] * inv1, acc[2*c+1][3] * inv1, ph[c][3], pl[c][3]);
    }
#pragma unroll
    for (int i = 0; i < 16; i++)
#pragma unroll
        for (int j = 0; j < 4; j++) acc[i][j] = 0.f;

    // ---- Phase 3: out = P * V (8 k-chunks) ----
    for (int v = 0; v < 8; v++) {
        CPWAIT2();
        __syncthreads();
        if (v + 3 < 8) loadV(v + 3);
        CPCOMMIT();

        const uint32_t ks = sb + ATT_KST + (uint32_t)((v & 3) * 8704);
#pragma unroll
        for (int gp = 0; gp < 4; gp++) {
            uint32_t b0h[4], b0l[4], b1h[4], b1l[4];
            uint32_t a0 = ks + kr * 272 + ((2 * gp) * 16 + nf) * 2;
            uint32_t a1 = ks + kr * 272 + ((2 * gp + 1) * 16 + nf) * 2;
            ldsm4t(b0h, a0); ldsm4t(b0l, a0 + 4352);
            ldsm4t(b1h, a1); ldsm4t(b1l, a1 + 4352);
            float* c0 = acc[4 * gp],     *c1 = acc[4 * gp + 1];
            float* c2 = acc[4 * gp + 2], *c3 = acc[4 * gp + 3];
            mma_bf16(c0, ph[v], b0h);  mma_bf16(c1, ph[v], b0h + 2);
            mma_bf16(c2, ph[v], b1h);  mma_bf16(c3, ph[v], b1h + 2);
            mma_bf16(c0, pl[v], b0h);  mma_bf16(c1, pl[v], b0h + 2);
            mma_bf16(c2, pl[v], b1h);  mma_bf16(c3, pl[v], b1h + 2);
            mma_bf16(c0, ph[v], b0l);  mma_bf16(c1, ph[v], b0l + 2);
            mma_bf16(c2, ph[v], b1l);  mma_bf16(c3, ph[v], b1l + 2);
        }
    }

    // ---- write att hi/lo planes ----
    {
        const int g = lane >> 2, c2 = (lane & 3) * 2;
        const size_t r0 = bhoff + (size_t)(w * 16 + g) * 128;
#pragma unroll
        for (int nt = 0; nt < 16; nt++) {
            int col = nt * 8 + c2;
            uint32_t hh, ll;
            packsplit2(acc[nt][0], acc[nt][1], hh, ll);
            *(uint32_t*)(ath + r0 + col) = hh;
            *(uint32_t*)(atl + r0 + col) = ll;
            packsplit2(acc[nt][2], acc[nt][3], hh, ll);
            *(uint32_t*)(ath + r0 + 8 * 128 + col) = hh;
            *(uint32_t*)(atl + r0 + 8 * 128 + col) = ll;
        }
    }
}

// ======================= launch ==============================================
extern "C" void kernel_launch(void* const* d_in, const int* in_sizes, int n_in,
                              void* d_out, int out_size)
{
    (void)in_sizes; (void)n_in; (void)out_size;
    const float* inp[3] = { (const float*)d_in[0], (const float*)d_in[1],
                            (const float*)d_in[2] };
    const float* W[8] = { (const float*)d_in[3], (const float*)d_in[4],
                          (const float*)d_in[5], (const float*)d_in[6],
                          (const float*)d_in[7], (const float*)d_in[8],
                          (const float*)d_in[9], (const float*)d_in[10] };
    const float* bo = (const float*)d_in[11];
    float* out = (float*)d_out;

    void* symp = nullptr;
    cudaGetSymbolAddress(&symp, g_bf);
    bf16* P = (bf16*)symp;
    bf16* inh = P;                      // 3 planes
    bf16* inl = P + 3ull * PLANE;       // 3 planes
    bf16* ohb = P + 6ull * PLANE;       // 7 planes: qw kw vw qp kp qc kc
    bf16* olb = P + 13ull * PLANE;      // 7 planes
    bf16* ath = P + 20ull * PLANE;
    bf16* atl = P + 21ull * PLANE;
    bf16* whb = P + 22ull * PLANE;      // 8 weight h planes
    bf16* wlb = whb + 8ull * WPLANE;    // 8 weight l planes

    cudaFuncSetAttribute(gemm_bf, cudaFuncAttributeMaxDynamicSharedMemorySize, GEMM_SMEM);
    cudaFuncSetAttribute(attn_mma, cudaFuncAttributeMaxDynamicSharedMemorySize, ATT_SMEM);

    // 0) split inputs (one launch)
    split_all<<<dim3(16384, 3), 256>>>(inp[0], inp[1], inp[2], inh, inl);

    // 1-2) transpose+split weights (two launches of 4)
    dim3 tgrid(32, 32, 4), tblk(32, 8);
    transpose4<<<tgrid, tblk>>>(W[0], W[1], W[2], W[3], whb, wlb);
    transpose4<<<tgrid, tblk>>>(W[4], W[5], W[6], W[7],
                                whb + 4ull * WPLANE, wlb + 4ull * WPLANE);

    // 3-5) combined projections -> hi/lo planes in head layout
    dim3 gblk(256);
    gemm_bf<<<dim3(24, 128), gblk, GEMM_SMEM>>>(
        inh, inl, whb, wlb,
        nullptr, ohb, olb, nullptr, 128, 1024, 16384, 128);                 // words: q,k,v
    gemm_bf<<<dim3(16, 128), gblk, GEMM_SMEM>>>(
        inh + PLANE, inl + PLANE, whb + 3ull * WPLANE, wlb + 3ull * WPLANE,
        nullptr, ohb + 3ull * PLANE, olb + 3ull * PLANE, nullptr,
        128, 1024, 16384, 128);                                             // position: q,k
    gemm_bf<<<dim3(16, 128), gblk, GEMM_SMEM>>>(
        inh + 2ull * PLANE, inl + 2ull * PLANE,
        whb + 5ull * WPLANE, wlb + 5ull * WPLANE,
        nullptr, ohb + 5ull * PLANE, olb + 5ull * PLANE, nullptr,
        128, 1024, 16384, 128);                                             // conscious: q,k

    // 6) attention -> att planes
    attn_mma<<<1024, gblk, ATT_SMEM>>>(ohb, olb, ath, atl);

    // 7) final GEMM: att * Wo^T + bias -> f32 out (row-major)
    gemm_bf<<<dim3(8, 128), gblk, GEMM_SMEM>>>(
        ath, atl, whb + 7ull * WPLANE, wlb + 7ull * WPLANE,
        out, nullptr, nullptr, bo, 16384, 128, 128, 1024);
}